// round 9
// baseline (speedup 1.0000x reference)
#include <cuda_runtime.h>
#include <cstdint>

// ALIF forward scan — cp.async smem-ring pipeline.
// x_seq: [T, n_flat] fp32; state v, a: [n_flat]; out spikes [T, n_flat] fp32.
// Per step: v = dv*v + x; th = th0 + beta*a; s = (v>th); v -= s*th; a = da*a + s.
//
// Thread-per-neuron. Loads stream through a 6-batch x 8-step smem ring filled
// by cp.async (4B per thread per step). commit_group per batch + wait_group(4)
// give exact completion control: batch j is guaranteed done while 4 newer
// batches (32 steps) remain in flight -> zero exposed DRAM latency, no
// scoreboard-slot aliasing (the failure mode of a deep register ring).

#define BS 8      // timesteps per batch
#define NB 6      // ring batches (12 KB smem)
#define BLKN 64   // neurons (threads) per CTA

__device__ __forceinline__ float alif_step(float& v, float& a, float xv,
                                           float dv, float da, float th0, float beta) {
    v = fmaf(dv, v, xv);
    float th = fmaf(beta, a, th0);
    float s = (v > th) ? 1.0f : 0.0f;
    v = fmaf(-s, th, v);
    a = fmaf(da, a, s);
    return s;
}

__device__ __forceinline__ void cp_async4(unsigned int smem_dst, const float* gsrc) {
    asm volatile("cp.async.ca.shared.global [%0], [%1], 4;\n"
                 :: "r"(smem_dst), "l"(gsrc) : "memory");
}
__device__ __forceinline__ void cp_commit() {
    asm volatile("cp.async.commit_group;\n" ::: "memory");
}
template <int N>
__device__ __forceinline__ void cp_wait() {
    asm volatile("cp.async.wait_group %0;\n" :: "n"(N) : "memory");
}

__global__ __launch_bounds__(BLKN)
void ALIF_24309514895931_kernel(const float* __restrict__ x,
                                const float* __restrict__ v0,
                                const float* __restrict__ a0,
                                const float* __restrict__ dv_p,
                                const float* __restrict__ da_p,
                                const float* __restrict__ th_p,
                                const float* __restrict__ beta_p,
                                float* __restrict__ out,
                                int n_flat, int T) {
    __shared__ float ring[NB * BS * BLKN];   // 12 KB

    int tid = threadIdx.x;
    int i = blockIdx.x * BLKN + tid;
    if (i >= n_flat) return;

    const float dv   = *dv_p;
    const float da   = *da_p;
    const float th0  = *th_p;
    const float beta = *beta_p;

    float v = v0[i];
    float a = a0[i];

    const float* xp = x + i;
    float* op = out + i;
    const unsigned int stride = (unsigned int)n_flat;

    // smem byte address of this thread's lane in the ring
    unsigned int smem_lane =
        (unsigned int)__cvta_generic_to_shared(ring) + (unsigned int)tid * 4u;
    const float* ring_lane = ring + tid;   // generic-side view for LDS

    const int nbatch = T / BS;

    // ---- Prologue: issue batches 0..NB-2 (up to 5 groups) ----
    int pro = (nbatch < NB - 1) ? nbatch : (NB - 1);
    for (int b = 0; b < pro; b++) {
        const float* src = xp + (size_t)b * BS * stride;
        unsigned int dst = smem_lane + (unsigned int)b * (BS * BLKN * 4);
        #pragma unroll
        for (int k = 0; k < BS; k++)
            cp_async4(dst + (unsigned int)k * (BLKN * 4), src + (size_t)k * stride);
        cp_commit();
    }

    // ---- Main loop ----
    int slot_issue = pro % NB;     // ring slot for next issued batch
    int slot_cons  = 0;            // ring slot for batch being consumed
    for (int j = 0; j < nbatch; j++) {
        // Issue batch j+NB-1 (if any), then always commit (empty groups keep
        // the wait_group accounting exact near the end of the stream).
        int bi = j + NB - 1;
        if (bi < nbatch) {
            const float* src = xp + (size_t)bi * BS * stride;
            unsigned int dst = smem_lane + (unsigned int)slot_issue * (BS * BLKN * 4);
            #pragma unroll
            for (int k = 0; k < BS; k++)
                cp_async4(dst + (unsigned int)k * (BLKN * 4), src + (size_t)k * stride);
            if (++slot_issue == NB) slot_issue = 0;
        }
        cp_commit();

        // All but the newest NB-2 groups complete => batch j is resident.
        cp_wait<NB - 2>();

        // Batched LDS into regs (latencies overlap), then serial compute.
        const float* rp = ring_lane + slot_cons * (BS * BLKN);
        float xs[BS];
        #pragma unroll
        for (int k = 0; k < BS; k++)
            xs[k] = rp[k * BLKN];

        unsigned int obase = (unsigned int)j * BS * stride;
        #pragma unroll
        for (int k = 0; k < BS; k++) {
            float s = alif_step(v, a, xs[k], dv, da, th0, beta);
            __stcs(op + obase + (unsigned int)k * stride, s);
        }
        if (++slot_cons == NB) slot_cons = 0;
    }

    // ---- Tail (T not a multiple of BS) ----
    for (int t = nbatch * BS; t < T; t++) {
        float xv = __ldcs(xp + (unsigned int)t * stride);
        float s = alif_step(v, a, xv, dv, da, th0, beta);
        __stcs(op + (unsigned int)t * stride, s);
    }
}

extern "C" void kernel_launch(void* const* d_in, const int* in_sizes, int n_in,
                              void* d_out, int out_size) {
    // metadata order: x_seq, v, a, decay_v, decay_a, threshold, beta, alpha
    const float* x      = (const float*)d_in[0];
    const float* v0     = (const float*)d_in[1];
    const float* a0     = (const float*)d_in[2];
    const float* dv_p   = (const float*)d_in[3];
    const float* da_p   = (const float*)d_in[4];
    const float* th_p   = (const float*)d_in[5];
    const float* beta_p = (const float*)d_in[6];
    // alpha (d_in[7]) only affects backward surrogate; unused in forward.

    int n_flat = in_sizes[1];
    int T      = in_sizes[0] / n_flat;

    float* out = (float*)d_out;

    int blocks = (n_flat + BLKN - 1) / BLKN;   // 1024 for n_flat=65536
    ALIF_24309514895931_kernel<<<blocks, BLKN>>>(
        x, v0, a0, dv_p, da_p, th_p, beta_p, out, n_flat, T);
}

// round 10
// speedup vs baseline: 1.2468x; 1.2468x over previous
#include <cuda_runtime.h>
#include <cstdint>

// ALIF forward scan — quad-buffered register pipeline.
// x_seq: [T, n_flat] fp32; state v, a: [n_flat]; out spikes [T, n_flat] fp32.
// Per step: v = dv*v + x; th = th0 + beta*a; s = (v>th); v -= s*th; a = da*a + s.
//
// Thread-per-neuron, sequential T. Four distinct 8-element load batches in a
// fixed 4-phase rotation: batch j is consumed 3 batches (24 steps) after its
// loads issue. With ~1-2 scoreboard slots per batch-block and only 3 batches
// in flight, batch waits are precise (no slot aliasing across the 6 SB slots,
// which was the exposure in the 32-deep single-array ring).

#define U 8       // timesteps per batch
#define BLKN 64   // threads per CTA

__device__ __forceinline__ float alif_step(float& v, float& a, float xv,
                                           float dv, float da, float th0, float beta) {
    v = fmaf(dv, v, xv);
    float th = fmaf(beta, a, th0);
    float s = (v > th) ? 1.0f : 0.0f;
    v = fmaf(-s, th, v);
    a = fmaf(da, a, s);
    return s;
}

__global__ __launch_bounds__(BLKN)
void ALIF_24309514895931_kernel(const float* __restrict__ x,
                                const float* __restrict__ v0,
                                const float* __restrict__ a0,
                                const float* __restrict__ dv_p,
                                const float* __restrict__ da_p,
                                const float* __restrict__ th_p,
                                const float* __restrict__ beta_p,
                                float* __restrict__ out,
                                int n_flat, int T) {
    int i = blockIdx.x * BLKN + threadIdx.x;
    if (i >= n_flat) return;

    const float dv   = *dv_p;
    const float da   = *da_p;
    const float th0  = *th_p;
    const float beta = *beta_p;

    float v = v0[i];
    float a = a0[i];

    const float* xp = x + i;
    float* op = out + i;
    const unsigned int stride = (unsigned int)n_flat;

    const int nb = T / U;

    float b0[U], b1[U], b2[U], b3[U];

#define LOADBLK(buf, bi)                                                    \
    {                                                                       \
        unsigned int base = (unsigned int)(bi) * U * stride;                \
        _Pragma("unroll")                                                   \
        for (int k = 0; k < U; k++)                                         \
            (buf)[k] = __ldcs(xp + base + (unsigned int)k * stride);        \
    }

#define COMPBLK(buf, bi)                                                    \
    {                                                                       \
        unsigned int base = (unsigned int)(bi) * U * stride;                \
        _Pragma("unroll")                                                   \
        for (int k = 0; k < U; k++) {                                       \
            float s = alif_step(v, a, (buf)[k], dv, da, th0, beta);         \
            __stcs(op + base + (unsigned int)k * stride, s);                \
        }                                                                   \
    }

    if (nb >= 4) {
        // Prologue: batches 0,1,2 in flight.
        LOADBLK(b0, 0);
        LOADBLK(b1, 1);
        LOADBLK(b2, 2);

        int g = 0;
        // Main 4-phase rotation: load g+3+p while computing g+p.
        for (; g + 4 <= nb; g += 4) {
            if (g + 3 < nb) LOADBLK(b3, g + 3);
            COMPBLK(b0, g);
            if (g + 4 < nb) LOADBLK(b0, g + 4);
            COMPBLK(b1, g + 1);
            if (g + 5 < nb) LOADBLK(b1, g + 5);
            COMPBLK(b2, g + 2);
            if (g + 6 < nb) LOADBLK(b2, g + 6);
            COMPBLK(b3, g + 3);
        }
        // Remainder batches (<4): already loaded by the guarded loads above,
        // in rotation order b0,b1,b2.
        int r = nb - g;
        if (r > 0) COMPBLK(b0, g);
        if (r > 1) COMPBLK(b1, g + 1);
        if (r > 2) COMPBLK(b2, g + 2);
    } else {
        for (int b = 0; b < nb; b++) {
            LOADBLK(b0, b);
            COMPBLK(b0, b);
        }
    }

    // Tail (T not a multiple of U).
    for (int t = nb * U; t < T; t++) {
        float xv = __ldcs(xp + (unsigned int)t * stride);
        float s = alif_step(v, a, xv, dv, da, th0, beta);
        __stcs(op + (unsigned int)t * stride, s);
    }
#undef LOADBLK
#undef COMPBLK
}

extern "C" void kernel_launch(void* const* d_in, const int* in_sizes, int n_in,
                              void* d_out, int out_size) {
    // metadata order: x_seq, v, a, decay_v, decay_a, threshold, beta, alpha
    const float* x      = (const float*)d_in[0];
    const float* v0     = (const float*)d_in[1];
    const float* a0     = (const float*)d_in[2];
    const float* dv_p   = (const float*)d_in[3];
    const float* da_p   = (const float*)d_in[4];
    const float* th_p   = (const float*)d_in[5];
    const float* beta_p = (const float*)d_in[6];
    // alpha (d_in[7]) only affects backward surrogate; unused in forward.

    int n_flat = in_sizes[1];
    int T      = in_sizes[0] / n_flat;

    float* out = (float*)d_out;

    int blocks = (n_flat + BLKN - 1) / BLKN;   // 1024 for n_flat=65536
    ALIF_24309514895931_kernel<<<blocks, BLKN>>>(
        x, v0, a0, dv_p, da_p, th_p, beta_p, out, n_flat, T);
}